// round 15
// baseline (speedup 1.0000x reference)
#include <cuda_runtime.h>
#include <cuda_fp16.h>
#include <math.h>
#include <stdint.h>

#define BN 4
#define SN 2048
#define HN 1024
#define MTOT (BN * SN)

// ---------------------------------------------------------------------------
// Scratch (__device__ globals; allocation-free rule)
// ---------------------------------------------------------------------------
__device__ __half g_xh[(size_t)MTOT * HN];
__device__ __half g_Wqh[(size_t)HN * HN];
__device__ __half g_Wkh[(size_t)HN * HN];
__device__ __half g_Wvh[(size_t)HN * HN];
__device__ __half g_Qh[(size_t)MTOT * HN];
__device__ __half g_KhA[(size_t)MTOT * HN];
__device__ __half g_Vth[(size_t)BN * HN * SN];
__device__ float  g_P[(size_t)BN * SN * SN];
__device__ __half g_Ph[(size_t)BN * SN * SN];

// ---------------------------------------------------------------------------
// Helpers (compute_103-safe: ldmatrix + mma.sync + cp.async only)
// ---------------------------------------------------------------------------
__device__ __forceinline__ uint32_t smem_u32(const void* p) {
    uint32_t a;
    asm("{ .reg .u64 t; cvta.to.shared.u64 t, %1; cvt.u32.u64 %0, t; }" : "=r"(a) : "l"(p));
    return a;
}
__device__ __forceinline__ void ldsm_x4(uint32_t* r, uint32_t a) {
    asm volatile("ldmatrix.sync.aligned.m8n8.x4.shared.b16 {%0,%1,%2,%3}, [%4];"
                 : "=r"(r[0]), "=r"(r[1]), "=r"(r[2]), "=r"(r[3]) : "r"(a));
}
__device__ __forceinline__ void mma_f16(float* c, const uint32_t* a,
                                        uint32_t b0, uint32_t b1) {
    asm volatile("mma.sync.aligned.m16n8k16.row.col.f32.f16.f16.f32 "
                 "{%0,%1,%2,%3}, {%4,%5,%6,%7}, {%8,%9}, {%0,%1,%2,%3};"
                 : "+f"(c[0]), "+f"(c[1]), "+f"(c[2]), "+f"(c[3])
                 : "r"(a[0]), "r"(a[1]), "r"(a[2]), "r"(a[3]), "r"(b0), "r"(b1));
}
#define CP_COMMIT() asm volatile("cp.async.commit_group;" ::: "memory")
#define CP_WAIT2()  asm volatile("cp.async.wait_group 2;" ::: "memory")

// ---------------------------------------------------------------------------
// Unified NT GEMM via mma.sync fp16 (1-pass):
//   C[M,N] = scale * sum_k A[m,k]*B[n,k] + bias
// Tile 128x128, BK=64 (128B rows, SW128 xor swizzle), 256 threads,
// warp grid 4(m)x2(n), warp tile 32x64. 4-stage cp.async pipeline.
// Mainloop: fragment double-buffering across ks (prefetch ks+1 while
// issuing ks's HMMAs) + XOR-delta swizzled addressing (consecutive ks
// atoms differ by constant XOR 0x20/0x60/0x20, row-independent).
// biasMode: 0 none, 1 bias[col], 2 bias[row].  outMode: 0 fp32, 1 fp16.
// Requires M%128==0, N%128==0, K%64==0, K>=256.
// ---------------------------------------------------------------------------
#define TILE_B  16384              // 128 rows x 128B
#define STG_B   (2 * TILE_B)       // 32 KB per stage
#define NST     4                  // 128 KB total

__global__ __launch_bounds__(256, 1)
void gemm128(const __half* __restrict__ A, const __half* __restrict__ B,
             const float* __restrict__ bias, int biasMode, float scale,
             float* __restrict__ Cf, __half* __restrict__ Ch,
             int outMode, int K, int ldc,
             size_t szA, size_t szB, size_t szC)
{
    extern __shared__ char smem[];
    const uint32_t sb = smem_u32(smem);
    const int tid = threadIdx.x, lane = tid & 31, wid = tid >> 5;
    const int wm = wid & 3, wn = wid >> 2;   // 4 x 2 warp grid, warp tile 32x64

    A += (size_t)blockIdx.z * szA;
    B += (size_t)blockIdx.z * szB;
    if (outMode == 0) Cf += (size_t)blockIdx.z * szC;
    else              Ch += (size_t)blockIdx.z * szC;

    const int rowBase = blockIdx.y * 128;
    const int colBase = blockIdx.x * 128;

    const __half* tA = A + (size_t)rowBase * K;
    const __half* tB = B + (size_t)colBase * K;

    const int NK = K >> 6;

    auto load_tile = [&](uint32_t dst, const __half* g) {
        #pragma unroll
        for (int i = 0; i < 4; i++) {
            int idx = i * 256 + tid;
            int row = idx >> 3;
            int kb  = idx & 7;
            uint32_t off = row * 128 + kb * 16;
            uint32_t sw  = off ^ ((off >> 3) & 0x70);
            const void* src = (const void*)(g + (size_t)row * K + kb * 8);
            asm volatile("cp.async.cg.shared.global [%0], [%1], 16;"
                         :: "r"(dst + sw), "l"(src));
        }
    };
    auto load_stage = [&](int buf, int c) {
        uint32_t st = sb + buf * STG_B;
        size_t ko = (size_t)c * 64;
        load_tile(st, tA + ko);
        load_tile(st + TILE_B, tB + ko);
        CP_COMMIT();
    };

    // accumulators: 2 m16-tiles x 8 n8-cols x 4 = 64 fp32
    float acc[2][8][4];
    #pragma unroll
    for (int i = 0; i < 2; i++)
        #pragma unroll
        for (int j = 0; j < 8; j++)
            #pragma unroll
            for (int q = 0; q < 4; q++) acc[i][j][q] = 0.0f;

    const int lm = lane & 15;
    const int lk = lane >> 4;
    int rA[2], rB[4];
    #pragma unroll
    for (int i = 0; i < 2; i++) rA[i] = wm * 32 + i * 16 + lm;
    #pragma unroll
    for (int g = 0; g < 4; g++) rB[g] = wn * 64 + g * 16 + lm;

    // loop-invariant parts of the ldmatrix addresses (stage-relative)
    uint32_t aOff[2], bOff[4];
    #pragma unroll
    for (int i = 0; i < 2; i++)
        aOff[i] = rA[i] * 128 + (uint32_t)((lk ^ (rA[i] & 7)) << 4);
    #pragma unroll
    for (int g = 0; g < 4; g++)
        bOff[g] = TILE_B + rB[g] * 128 + (uint32_t)((lk ^ (rB[g] & 7)) << 4);

    // prologue: fill 3 of 4 stages (NK >= 4 for all call sites)
    load_stage(0, 0);
    load_stage(1, 1);
    load_stage(2, 2);

    for (int c = 0; c < NK; c++) {
        CP_WAIT2();
        __syncthreads();
        if (c + 3 < NK) load_stage((c + 3) & 3, c + 3);
        else            CP_COMMIT();   // empty group keeps wait_group math valid

        const uint32_t stage = sb + (c & 3) * STG_B;

        // ks=0 fragment addresses; subsequent ks via constant XOR deltas
        uint32_t aAd[2], bAd[4];
        #pragma unroll
        for (int i = 0; i < 2; i++) aAd[i] = stage + aOff[i];
        #pragma unroll
        for (int g = 0; g < 4; g++) bAd[g] = stage + bOff[g];

        uint32_t af[2][2][4], bfr[2][4][4];
        #pragma unroll
        for (int i = 0; i < 2; i++) ldsm_x4(af[0][i], aAd[i]);
        #pragma unroll
        for (int g = 0; g < 4; g++) ldsm_x4(bfr[0][g], bAd[g]);

        #pragma unroll
        for (int ks = 0; ks < 4; ks++) {
            const int cur = ks & 1, nxt = cur ^ 1;
            if (ks < 3) {
                const uint32_t d = (ks == 1) ? 0x60u : 0x20u;
                #pragma unroll
                for (int i = 0; i < 2; i++) { aAd[i] ^= d; ldsm_x4(af[nxt][i], aAd[i]); }
                #pragma unroll
                for (int g = 0; g < 4; g++) { bAd[g] ^= d; ldsm_x4(bfr[nxt][g], bAd[g]); }
            }
            #pragma unroll
            for (int i = 0; i < 2; i++)
                #pragma unroll
                for (int g = 0; g < 4; g++) {
                    mma_f16(acc[i][2 * g + 0], af[cur][i], bfr[cur][g][0], bfr[cur][g][2]);
                    mma_f16(acc[i][2 * g + 1], af[cur][i], bfr[cur][g][1], bfr[cur][g][3]);
                }
        }
    }

    // epilogue: scale + bias
    #pragma unroll
    for (int i = 0; i < 2; i++) {
        #pragma unroll
        for (int half = 0; half < 2; half++) {
            const int row = rowBase + wm * 32 + i * 16 + (lane >> 2) + half * 8;
            const float rb = (biasMode == 2) ? bias[row] : 0.0f;
            #pragma unroll
            for (int j = 0; j < 8; j++) {
                const int col = colBase + wn * 64 + j * 8 + (lane & 3) * 2;
                float v0 = acc[i][j][half * 2 + 0] * scale;
                float v1 = acc[i][j][half * 2 + 1] * scale;
                if (biasMode == 1) { v0 += bias[col]; v1 += bias[col + 1]; }
                else               { v0 += rb;        v1 += rb; }
                const size_t base = (size_t)row * ldc + col;
                if (outMode == 0) {
                    float2 o; o.x = v0; o.y = v1;
                    *(float2*)(Cf + base) = o;
                } else {
                    __half2 hh; hh.x = __float2half_rn(v0); hh.y = __float2half_rn(v1);
                    *(__half2*)(Ch + base) = hh;
                }
            }
        }
    }
}

// ---------------------------------------------------------------------------
// merged fp32 -> fp16 rounding for x, Wq, Wk, Wv (one launch)
// ---------------------------------------------------------------------------
__global__ __launch_bounds__(256) void round_all(
    const float* __restrict__ x,  __half* __restrict__ xh,
    const float* __restrict__ Wq, __half* __restrict__ Wqh,
    const float* __restrict__ Wk, __half* __restrict__ Wkh,
    const float* __restrict__ Wv, __half* __restrict__ Wvh)
{
    int b = blockIdx.x;
    const float* in; __half* out; size_t off;
    if (b < 8192)       { in = x;  out = xh;  off = (size_t)b * 1024; }
    else if (b < 9216)  { in = Wq; out = Wqh; off = (size_t)(b - 8192) * 1024; }
    else if (b < 10240) { in = Wk; out = Wkh; off = (size_t)(b - 9216) * 1024; }
    else                { in = Wv; out = Wvh; off = (size_t)(b - 10240) * 1024; }
    size_t i = off + (size_t)threadIdx.x * 4;
    float4 v = *(const float4*)(in + i);
    __half2 ha; ha.x = __float2half_rn(v.x); ha.y = __float2half_rn(v.y);
    __half2 hb; hb.x = __float2half_rn(v.z); hb.y = __float2half_rn(v.w);
    *(__half2*)(out + i) = ha; *(__half2*)(out + i + 2) = hb;
}

// ---------------------------------------------------------------------------
// row softmax: fp32 in, fp16 out. One block per row of 2048.
// ---------------------------------------------------------------------------
__global__ __launch_bounds__(256) void softmax_h(
    const float* __restrict__ P, __half* __restrict__ Ph, int n)
{
    const float* row = P + (size_t)blockIdx.x * n;
    __half* oh = Ph + (size_t)blockIdx.x * n;
    const int tid = threadIdx.x, lane = tid & 31, wd = tid >> 5;
    __shared__ float red[8];

    float v[8]; float m = -INFINITY;
    #pragma unroll
    for (int i = 0; i < 8; i++) { v[i] = row[tid + i * 256]; m = fmaxf(m, v[i]); }
    #pragma unroll
    for (int o = 16; o > 0; o >>= 1) m = fmaxf(m, __shfl_xor_sync(~0u, m, o));
    if (lane == 0) red[wd] = m;
    __syncthreads();
    float mb = red[0];
    #pragma unroll
    for (int w = 1; w < 8; w++) mb = fmaxf(mb, red[w]);
    __syncthreads();

    float s = 0.0f;
    #pragma unroll
    for (int i = 0; i < 8; i++) { v[i] = __expf(v[i] - mb); s += v[i]; }
    #pragma unroll
    for (int o = 16; o > 0; o >>= 1) s += __shfl_xor_sync(~0u, s, o);
    if (lane == 0) red[wd] = s;
    __syncthreads();
    float sb = 0.0f;
    #pragma unroll
    for (int w = 0; w < 8; w++) sb += red[w];
    const float r = 1.0f / sb;

    #pragma unroll
    for (int i = 0; i < 8; i++)
        oh[tid + i * 256] = __float2half_rn(v[i] * r);
}

// ---------------------------------------------------------------------------
extern "C" void kernel_launch(void* const* d_in, const int* in_sizes, int n_in,
                              void* d_out, int out_size)
{
    (void)in_sizes; (void)n_in; (void)out_size;
    const float* x  = (const float*)d_in[0];
    const float* Wq = (const float*)d_in[1];
    const float* bq = (const float*)d_in[2];
    const float* Wk = (const float*)d_in[3];
    const float* bk = (const float*)d_in[4];
    const float* Wv = (const float*)d_in[5];
    const float* bv = (const float*)d_in[6];
    float* out = (float*)d_out;

    const int smem = NST * STG_B;   // 128 KB
    cudaFuncSetAttribute(gemm128, cudaFuncAttributeMaxDynamicSharedMemorySize, smem);

    __half *xh, *Wqh, *Wkh, *Wvh, *Qh, *Kh, *Vth, *Ph;
    float *P;
    cudaGetSymbolAddress((void**)&xh, g_xh);
    cudaGetSymbolAddress((void**)&Wqh, g_Wqh);
    cudaGetSymbolAddress((void**)&Wkh, g_Wkh);
    cudaGetSymbolAddress((void**)&Wvh, g_Wvh);
    cudaGetSymbolAddress((void**)&Qh, g_Qh);
    cudaGetSymbolAddress((void**)&Kh, g_KhA);
    cudaGetSymbolAddress((void**)&Vth, g_Vth);
    cudaGetSymbolAddress((void**)&P, g_P);
    cudaGetSymbolAddress((void**)&Ph, g_Ph);

    // 0) round all fp32 inputs to fp16 in one launch
    round_all<<<11264, 256>>>(x, xh, Wq, Wqh, Wk, Wkh, Wv, Wvh);

    // 1) Q = xh @ Wqh^T + bq -> Qh;  K = xh @ Wkh^T + bk -> Kh
    {
        dim3 g(HN / 128, MTOT / 128, 1);
        gemm128<<<g, 256, smem>>>(xh, Wqh, bq, 1, 1.0f,
                                  nullptr, Qh, 1, HN, HN, 0, 0, 0);
        gemm128<<<g, 256, smem>>>(xh, Wkh, bk, 1, 1.0f,
                                  nullptr, Kh, 1, HN, HN, 0, 0, 0);
    }
    // 2) Vt_b = Wvh @ xh_b^T + bv[row] -> Vth
    {
        dim3 g(SN / 128, HN / 128, BN);
        gemm128<<<g, 256, smem>>>(Wvh, xh, bv, 2, 1.0f,
                                  nullptr, Vth, 1, HN, SN,
                                  0, (size_t)SN * HN, (size_t)HN * SN);
    }
    // 3) scores = Qh_b @ Kh_b^T / 32 -> fp32 P
    {
        dim3 g(SN / 128, SN / 128, BN);
        gemm128<<<g, 256, smem>>>(Qh, Kh, nullptr, 0, 0.03125f,
                                  P, nullptr, 0, HN, SN,
                                  (size_t)SN * HN, (size_t)SN * HN, (size_t)SN * SN);
    }
    // 4) softmax rows -> Ph
    softmax_h<<<BN * SN, 256>>>(P, Ph, SN);

    // 5) out = Ph_b @ Vth_b^T -> fp32
    {
        dim3 g(HN / 128, SN / 128, BN);
        gemm128<<<g, 256, smem>>>(Ph, Vth, nullptr, 0, 1.0f,
                                  out, nullptr, 0, SN, HN,
                                  (size_t)SN * SN, (size_t)HN * SN, (size_t)SN * HN);
    }
}

// round 16
// speedup vs baseline: 1.1344x; 1.1344x over previous
#include <cuda_runtime.h>
#include <cuda_fp16.h>
#include <math.h>
#include <stdint.h>

#define BN 4
#define SN 2048
#define HN 1024
#define MTOT (BN * SN)

// ---------------------------------------------------------------------------
// Scratch (__device__ globals; allocation-free rule)
// ---------------------------------------------------------------------------
__device__ __half g_xh[(size_t)MTOT * HN];
__device__ __half g_Wqh[(size_t)HN * HN];
__device__ __half g_Wkh[(size_t)HN * HN];
__device__ __half g_Wvh[(size_t)HN * HN];
__device__ __half g_Qh[(size_t)MTOT * HN];
__device__ __half g_KhA[(size_t)MTOT * HN];
__device__ __half g_Vth[(size_t)BN * HN * SN];
__device__ float  g_P[(size_t)BN * SN * SN];
__device__ __half g_Ph[(size_t)BN * SN * SN];

// ---------------------------------------------------------------------------
// Helpers (compute_103-safe: ldmatrix + mma.sync + cp.async only)
// ---------------------------------------------------------------------------
__device__ __forceinline__ uint32_t smem_u32(const void* p) {
    uint32_t a;
    asm("{ .reg .u64 t; cvta.to.shared.u64 t, %1; cvt.u32.u64 %0, t; }" : "=r"(a) : "l"(p));
    return a;
}
__device__ __forceinline__ void ldsm_x4(uint32_t* r, uint32_t a) {
    asm volatile("ldmatrix.sync.aligned.m8n8.x4.shared.b16 {%0,%1,%2,%3}, [%4];"
                 : "=r"(r[0]), "=r"(r[1]), "=r"(r[2]), "=r"(r[3]) : "r"(a));
}
__device__ __forceinline__ void mma_f16(float* c, const uint32_t* a,
                                        uint32_t b0, uint32_t b1) {
    asm volatile("mma.sync.aligned.m16n8k16.row.col.f32.f16.f16.f32 "
                 "{%0,%1,%2,%3}, {%4,%5,%6,%7}, {%8,%9}, {%0,%1,%2,%3};"
                 : "+f"(c[0]), "+f"(c[1]), "+f"(c[2]), "+f"(c[3])
                 : "r"(a[0]), "r"(a[1]), "r"(a[2]), "r"(a[3]), "r"(b0), "r"(b1));
}
#define CP_COMMIT() asm volatile("cp.async.commit_group;" ::: "memory")
#define CP_WAIT0()  asm volatile("cp.async.wait_group 0;" ::: "memory")
#define CP_WAIT1()  asm volatile("cp.async.wait_group 1;" ::: "memory")

// ---------------------------------------------------------------------------
// Unified NT GEMM via mma.sync fp16 (1-pass):
//   C[M,N] = scale * sum_k A[m,k]*B[n,k] + bias
// Tile 128x128, BK=64 (128B rows, SW128 xor swizzle), 256 threads,
// warp grid 4(m)x2(n), warp tile 32x64. 3-stage cp.async pipeline,
// 96 KB smem -> OCCUPANCY 2 (2 CTAs/SM: 16 warps/SM + cross-CTA overlap;
// 124 regs x 256 thr x 2 = 63.5K < 64K RF).
// Mainloop: fragment double-buffering across ks + XOR-delta addressing.
// biasMode: 0 none, 1 bias[col], 2 bias[row].  outMode: 0 fp32, 1 fp16.
// Requires M%128==0, N%128==0, K%64==0, K>=128.
// ---------------------------------------------------------------------------
#define TILE_B  16384              // 128 rows x 128B
#define STG_B   (2 * TILE_B)       // 32 KB per stage
#define NST     3                  // 96 KB total

__global__ __launch_bounds__(256, 2)
void gemm128(const __half* __restrict__ A, const __half* __restrict__ B,
             const float* __restrict__ bias, int biasMode, float scale,
             float* __restrict__ Cf, __half* __restrict__ Ch,
             int outMode, int K, int ldc,
             size_t szA, size_t szB, size_t szC)
{
    extern __shared__ char smem[];
    const uint32_t sb = smem_u32(smem);
    const int tid = threadIdx.x, lane = tid & 31, wid = tid >> 5;
    const int wm = wid & 3, wn = wid >> 2;   // 4 x 2 warp grid, warp tile 32x64

    A += (size_t)blockIdx.z * szA;
    B += (size_t)blockIdx.z * szB;
    if (outMode == 0) Cf += (size_t)blockIdx.z * szC;
    else              Ch += (size_t)blockIdx.z * szC;

    const int rowBase = blockIdx.y * 128;
    const int colBase = blockIdx.x * 128;

    const __half* tA = A + (size_t)rowBase * K;
    const __half* tB = B + (size_t)colBase * K;

    const int NK = K >> 6;

    auto load_tile = [&](uint32_t dst, const __half* g) {
        #pragma unroll
        for (int i = 0; i < 4; i++) {
            int idx = i * 256 + tid;
            int row = idx >> 3;
            int kb  = idx & 7;
            uint32_t off = row * 128 + kb * 16;
            uint32_t sw  = off ^ ((off >> 3) & 0x70);
            const void* src = (const void*)(g + (size_t)row * K + kb * 8);
            asm volatile("cp.async.cg.shared.global [%0], [%1], 16;"
                         :: "r"(dst + sw), "l"(src));
        }
    };
    auto load_stage = [&](int buf, int c) {
        uint32_t st = sb + buf * STG_B;
        size_t ko = (size_t)c * 64;
        load_tile(st, tA + ko);
        load_tile(st + TILE_B, tB + ko);
        CP_COMMIT();
    };

    // accumulators: 2 m16-tiles x 8 n8-cols x 4 = 64 fp32
    float acc[2][8][4];
    #pragma unroll
    for (int i = 0; i < 2; i++)
        #pragma unroll
        for (int j = 0; j < 8; j++)
            #pragma unroll
            for (int q = 0; q < 4; q++) acc[i][j][q] = 0.0f;

    const int lm = lane & 15;
    const int lk = lane >> 4;
    int rA[2], rB[4];
    #pragma unroll
    for (int i = 0; i < 2; i++) rA[i] = wm * 32 + i * 16 + lm;
    #pragma unroll
    for (int g = 0; g < 4; g++) rB[g] = wn * 64 + g * 16 + lm;

    // loop-invariant ldmatrix address parts (stage-relative)
    uint32_t aOff[2], bOff[4];
    #pragma unroll
    for (int i = 0; i < 2; i++)
        aOff[i] = rA[i] * 128 + (uint32_t)((lk ^ (rA[i] & 7)) << 4);
    #pragma unroll
    for (int g = 0; g < 4; g++)
        bOff[g] = TILE_B + rB[g] * 128 + (uint32_t)((lk ^ (rB[g] & 7)) << 4);

    // prologue: fill 2 of 3 stages
    load_stage(0, 0);
    if (NK > 1) load_stage(1, 1);

    int buf = 0;
    for (int c = 0; c < NK; c++) {
        if (c < NK - 1) { CP_WAIT1(); } else { CP_WAIT0(); }
        __syncthreads();
        if (c + 2 < NK) {
            int nb = buf + 2; if (nb >= NST) nb -= NST;
            load_stage(nb, c + 2);
        }

        const uint32_t stage = sb + buf * STG_B;

        // ks=0 fragment addresses; subsequent ks via constant XOR deltas
        uint32_t aAd[2], bAd[4];
        #pragma unroll
        for (int i = 0; i < 2; i++) aAd[i] = stage + aOff[i];
        #pragma unroll
        for (int g = 0; g < 4; g++) bAd[g] = stage + bOff[g];

        uint32_t af[2][2][4], bfr[2][4][4];
        #pragma unroll
        for (int i = 0; i < 2; i++) ldsm_x4(af[0][i], aAd[i]);
        #pragma unroll
        for (int g = 0; g < 4; g++) ldsm_x4(bfr[0][g], bAd[g]);

        #pragma unroll
        for (int ks = 0; ks < 4; ks++) {
            const int cur = ks & 1, nxt = cur ^ 1;
            if (ks < 3) {
                const uint32_t d = (ks == 1) ? 0x60u : 0x20u;
                #pragma unroll
                for (int i = 0; i < 2; i++) { aAd[i] ^= d; ldsm_x4(af[nxt][i], aAd[i]); }
                #pragma unroll
                for (int g = 0; g < 4; g++) { bAd[g] ^= d; ldsm_x4(bfr[nxt][g], bAd[g]); }
            }
            #pragma unroll
            for (int i = 0; i < 2; i++)
                #pragma unroll
                for (int g = 0; g < 4; g++) {
                    mma_f16(acc[i][2 * g + 0], af[cur][i], bfr[cur][g][0], bfr[cur][g][2]);
                    mma_f16(acc[i][2 * g + 1], af[cur][i], bfr[cur][g][1], bfr[cur][g][3]);
                }
        }
        buf++; if (buf >= NST) buf = 0;
    }

    // epilogue: scale + bias
    #pragma unroll
    for (int i = 0; i < 2; i++) {
        #pragma unroll
        for (int half = 0; half < 2; half++) {
            const int row = rowBase + wm * 32 + i * 16 + (lane >> 2) + half * 8;
            const float rb = (biasMode == 2) ? bias[row] : 0.0f;
            #pragma unroll
            for (int j = 0; j < 8; j++) {
                const int col = colBase + wn * 64 + j * 8 + (lane & 3) * 2;
                float v0 = acc[i][j][half * 2 + 0] * scale;
                float v1 = acc[i][j][half * 2 + 1] * scale;
                if (biasMode == 1) { v0 += bias[col]; v1 += bias[col + 1]; }
                else               { v0 += rb;        v1 += rb; }
                const size_t base = (size_t)row * ldc + col;
                if (outMode == 0) {
                    float2 o; o.x = v0; o.y = v1;
                    *(float2*)(Cf + base) = o;
                } else {
                    __half2 hh; hh.x = __float2half_rn(v0); hh.y = __float2half_rn(v1);
                    *(__half2*)(Ch + base) = hh;
                }
            }
        }
    }
}

// ---------------------------------------------------------------------------
// merged fp32 -> fp16 rounding for x, Wq, Wk, Wv (one launch)
// ---------------------------------------------------------------------------
__global__ __launch_bounds__(256) void round_all(
    const float* __restrict__ x,  __half* __restrict__ xh,
    const float* __restrict__ Wq, __half* __restrict__ Wqh,
    const float* __restrict__ Wk, __half* __restrict__ Wkh,
    const float* __restrict__ Wv, __half* __restrict__ Wvh)
{
    int b = blockIdx.x;
    const float* in; __half* out; size_t off;
    if (b < 8192)       { in = x;  out = xh;  off = (size_t)b * 1024; }
    else if (b < 9216)  { in = Wq; out = Wqh; off = (size_t)(b - 8192) * 1024; }
    else if (b < 10240) { in = Wk; out = Wkh; off = (size_t)(b - 9216) * 1024; }
    else                { in = Wv; out = Wvh; off = (size_t)(b - 10240) * 1024; }
    size_t i = off + (size_t)threadIdx.x * 4;
    float4 v = *(const float4*)(in + i);
    __half2 ha; ha.x = __float2half_rn(v.x); ha.y = __float2half_rn(v.y);
    __half2 hb; hb.x = __float2half_rn(v.z); hb.y = __float2half_rn(v.w);
    *(__half2*)(out + i) = ha; *(__half2*)(out + i + 2) = hb;
}

// ---------------------------------------------------------------------------
// row softmax: fp32 in, fp16 out. One block per row of 2048.
// ---------------------------------------------------------------------------
__global__ __launch_bounds__(256) void softmax_h(
    const float* __restrict__ P, __half* __restrict__ Ph, int n)
{
    const float* row = P + (size_t)blockIdx.x * n;
    __half* oh = Ph + (size_t)blockIdx.x * n;
    const int tid = threadIdx.x, lane = tid & 31, wd = tid >> 5;
    __shared__ float red[8];

    float v[8]; float m = -INFINITY;
    #pragma unroll
    for (int i = 0; i < 8; i++) { v[i] = row[tid + i * 256]; m = fmaxf(m, v[i]); }
    #pragma unroll
    for (int o = 16; o > 0; o >>= 1) m = fmaxf(m, __shfl_xor_sync(~0u, m, o));
    if (lane == 0) red[wd] = m;
    __syncthreads();
    float mb = red[0];
    #pragma unroll
    for (int w = 1; w < 8; w++) mb = fmaxf(mb, red[w]);
    __syncthreads();

    float s = 0.0f;
    #pragma unroll
    for (int i = 0; i < 8; i++) { v[i] = __expf(v[i] - mb); s += v[i]; }
    #pragma unroll
    for (int o = 16; o > 0; o >>= 1) s += __shfl_xor_sync(~0u, s, o);
    if (lane == 0) red[wd] = s;
    __syncthreads();
    float sb = 0.0f;
    #pragma unroll
    for (int w = 0; w < 8; w++) sb += red[w];
    const float r = 1.0f / sb;

    #pragma unroll
    for (int i = 0; i < 8; i++)
        oh[tid + i * 256] = __float2half_rn(v[i] * r);
}

// ---------------------------------------------------------------------------
extern "C" void kernel_launch(void* const* d_in, const int* in_sizes, int n_in,
                              void* d_out, int out_size)
{
    (void)in_sizes; (void)n_in; (void)out_size;
    const float* x  = (const float*)d_in[0];
    const float* Wq = (const float*)d_in[1];
    const float* bq = (const float*)d_in[2];
    const float* Wk = (const float*)d_in[3];
    const float* bk = (const float*)d_in[4];
    const float* Wv = (const float*)d_in[5];
    const float* bv = (const float*)d_in[6];
    float* out = (float*)d_out;

    const int smem = NST * STG_B;   // 96 KB
    cudaFuncSetAttribute(gemm128, cudaFuncAttributeMaxDynamicSharedMemorySize, smem);

    __half *xh, *Wqh, *Wkh, *Wvh, *Qh, *Kh, *Vth, *Ph;
    float *P;
    cudaGetSymbolAddress((void**)&xh, g_xh);
    cudaGetSymbolAddress((void**)&Wqh, g_Wqh);
    cudaGetSymbolAddress((void**)&Wkh, g_Wkh);
    cudaGetSymbolAddress((void**)&Wvh, g_Wvh);
    cudaGetSymbolAddress((void**)&Qh, g_Qh);
    cudaGetSymbolAddress((void**)&Kh, g_KhA);
    cudaGetSymbolAddress((void**)&Vth, g_Vth);
    cudaGetSymbolAddress((void**)&P, g_P);
    cudaGetSymbolAddress((void**)&Ph, g_Ph);

    // 0) round all fp32 inputs to fp16 in one launch
    round_all<<<11264, 256>>>(x, xh, Wq, Wqh, Wk, Wkh, Wv, Wvh);

    // 1) Q = xh @ Wqh^T + bq -> Qh;  K = xh @ Wkh^T + bk -> Kh
    {
        dim3 g(HN / 128, MTOT / 128, 1);
        gemm128<<<g, 256, smem>>>(xh, Wqh, bq, 1, 1.0f,
                                  nullptr, Qh, 1, HN, HN, 0, 0, 0);
        gemm128<<<g, 256, smem>>>(xh, Wkh, bk, 1, 1.0f,
                                  nullptr, Kh, 1, HN, HN, 0, 0, 0);
    }
    // 2) Vt_b = Wvh @ xh_b^T + bv[row] -> Vth
    {
        dim3 g(SN / 128, HN / 128, BN);
        gemm128<<<g, 256, smem>>>(Wvh, xh, bv, 2, 1.0f,
                                  nullptr, Vth, 1, HN, SN,
                                  0, (size_t)SN * HN, (size_t)HN * SN);
    }
    // 3) scores = Qh_b @ Kh_b^T / 32 -> fp32 P
    {
        dim3 g(SN / 128, SN / 128, BN);
        gemm128<<<g, 256, smem>>>(Qh, Kh, nullptr, 0, 0.03125f,
                                  P, nullptr, 0, HN, SN,
                                  (size_t)SN * HN, (size_t)SN * HN, (size_t)SN * SN);
    }
    // 4) softmax rows -> Ph
    softmax_h<<<BN * SN, 256>>>(P, Ph, SN);

    // 5) out = Ph_b @ Vth_b^T -> fp32
    {
        dim3 g(HN / 128, SN / 128, BN);
        gemm128<<<g, 256, smem>>>(Ph, Vth, nullptr, 0, 1.0f,
                                  out, nullptr, 0, SN, HN,
                                  (size_t)SN * SN, (size_t)HN * SN, (size_t)SN * HN);
    }
}